// round 14
// baseline (speedup 1.0000x reference)
#include <cuda_runtime.h>
#include <math.h>

#define EMBD   64
#define DD     900
#define M64    64
#define KDIM   32768
#define NPAD   4608
#define SPLITK 8
#define KCHUNK (KDIM/SPLITK)
#define BK     32
#define BN     128
#define GITERS (KCHUNK/BK)
#define KT     8

// ------------------------- scratch (static, no allocs) ----------------------
__device__ float g_E[M64][KDIM];
__device__ float g_Cpart[SPLITK][M64][NPAD];
__device__ float g_Csum[M64][NPAD];
__device__ float g_conv[8][DD];
__device__ float g_Q[8][DD];
__device__ float g_K[8][DD];
__device__ float g_V[8][DD];
__device__ float g_attw[8][DD][DD];
__device__ float g_att[8][DD];
__device__ float g_base[8 * DD];
__device__ float g_s0[8 * DD];
__device__ float g_s1[8 * DD];

// ------------------------- f32x2 helpers ------------------------------------
__device__ __forceinline__ unsigned long long pk2(float x, float y) {
    unsigned long long r;
    asm("mov.b64 %0, {%1, %2};" : "=l"(r) : "f"(x), "f"(y));
    return r;
}
__device__ __forceinline__ void fma2(unsigned long long& d,
                                     unsigned long long a,
                                     unsigned long long b) {
    asm("fma.rn.f32x2 %0, %1, %2, %0;" : "+l"(d) : "l"(a), "l"(b));
}
__device__ __forceinline__ float2 unpk2(unsigned long long v) {
    float2 f;
    asm("mov.b64 {%0, %1}, %2;" : "=f"(f.x), "=f"(f.y) : "l"(v));
    return f;
}

// 1. E[m=(b*8+h)][i*512+w] = emb[x[b,h,w]][i]
__global__ void k_build_E(const int* __restrict__ x, const float* __restrict__ emb) {
    int m = blockIdx.y;
    int k = blockIdx.x * 256 + threadIdx.x;
    int w = k & 511, i = k >> 9;
    g_E[m][k] = emb[x[m * 512 + w] * 64 + i];
}

// 2. split-K GEMM: Cpart[slab] = E-slab * Wrows^T
__global__ __launch_bounds__(256, 2) void k_gemm(const float* __restrict__ w3,
                                                 const float* __restrict__ w5,
                                                 const float* __restrict__ w7) {
    __shared__ float As[BK][68];
    __shared__ float Bs[BK][BN + 4];
    __shared__ const float* rowp[BN];
    __shared__ int istr[BN];

    int tid  = threadIdx.x;
    int n0   = blockIdx.x * BN;
    int slab = blockIdx.y;

    if (tid < BN) {
        int n = n0 + tid;
        const float* arr; int kk, o, r;
        if (n < 900)       { arr = w3; kk = 3; o = n / 3;             r = n - o * 3; }
        else if (n < 2400) { arr = w5; kk = 5; int u = n - 900;  o = u / 5; r = u - o * 5; }
        else if (n < 4500) { arr = w7; kk = 7; int u = n - 2400; o = u / 7; r = u - o * 7; }
        else               { arr = w3; kk = 3; o = 0; r = 0; }
        rowp[tid] = arr + (size_t)o * (64 * kk * 512) + r * 512;
        istr[tid] = kk * 512;
    }
    __syncthreads();

    int arow = tid >> 2, aq = tid & 3;
    int brow = tid >> 1, bh = tid & 1;
    const float* browp = rowp[brow];
    int bistr = istr[brow];
    int tm8 = (tid >> 5) * 8;
    int tn4 = (tid & 31) * 4;
    int kbase = slab * KCHUNK;

    float4 sa[2], sb[4];
    {
        int k0 = kbase;
        int i0 = k0 >> 9, w0 = k0 & 511;
        const float4* ap = (const float4*)&g_E[arow][k0 + aq * 8];
        sa[0] = ap[0]; sa[1] = ap[1];
        const float4* bp = (const float4*)(browp + (size_t)i0 * bistr + w0 + bh * 16);
        sb[0] = bp[0]; sb[1] = bp[1]; sb[2] = bp[2]; sb[3] = bp[3];
    }

    unsigned long long acc[4][4];
#pragma unroll
    for (int i = 0; i < 4; i++)
#pragma unroll
        for (int j = 0; j < 4; j++) acc[i][j] = 0ull;

    for (int it = 0; it < GITERS; it++) {
        const float* av = (const float*)sa;
#pragma unroll
        for (int j = 0; j < 8; j++) As[aq * 8 + j][arow] = av[j];
        const float* bv = (const float*)sb;
#pragma unroll
        for (int j = 0; j < 16; j++) Bs[bh * 16 + j][brow] = bv[j];
        __syncthreads();

        if (it + 1 < GITERS) {
            int k0 = kbase + (it + 1) * BK;
            int i0 = k0 >> 9, w0 = k0 & 511;
            const float4* ap = (const float4*)&g_E[arow][k0 + aq * 8];
            sa[0] = ap[0]; sa[1] = ap[1];
            const float4* bp = (const float4*)(browp + (size_t)i0 * bistr + w0 + bh * 16);
            sb[0] = bp[0]; sb[1] = bp[1]; sb[2] = bp[2]; sb[3] = bp[3];
        }

#pragma unroll
        for (int k = 0; k < BK; k++) {
            const ulonglong2* ap2 = (const ulonglong2*)&As[k][tm8];
            ulonglong2 aA = ap2[0];
            ulonglong2 aB = ap2[1];
            float4 b4 = *(const float4*)&Bs[k][tn4];
            unsigned long long bb[4];
            bb[0] = pk2(b4.x, b4.x); bb[1] = pk2(b4.y, b4.y);
            bb[2] = pk2(b4.z, b4.z); bb[3] = pk2(b4.w, b4.w);
#pragma unroll
            for (int ni = 0; ni < 4; ni++) {
                fma2(acc[ni][0], aA.x, bb[ni]);
                fma2(acc[ni][1], aA.y, bb[ni]);
                fma2(acc[ni][2], aB.x, bb[ni]);
                fma2(acc[ni][3], aB.y, bb[ni]);
            }
        }
        __syncthreads();
    }

#pragma unroll
    for (int ni = 0; ni < 4; ni++) {
        int n = n0 + tn4 + ni;
#pragma unroll
        for (int mj = 0; mj < 4; mj++) {
            float2 f = unpk2(acc[ni][mj]);
            int m = tm8 + mj * 2;
            g_Cpart[slab][m][n]     = f.x;
            g_Cpart[slab][m + 1][n] = f.y;
        }
    }
}

// 3. split-K reduce
__global__ void k_reduceC() {
    int idx = blockIdx.x * 256 + threadIdx.x;
    const float* cp = (const float*)g_Cpart;
    float s = 0.f;
#pragma unroll
    for (int j = 0; j < SPLITK; j++) s += cp[(size_t)j * (M64 * NPAD) + idx];
    ((float*)g_Csum)[idx] = s;
}

// 4. bias + relu + max over H
__global__ void k_pool(const float* __restrict__ b3, const float* __restrict__ b5,
                       const float* __restrict__ b7) {
    int col = blockIdx.x * 128 + threadIdx.x;
    int b = blockIdx.y;
    if (col >= 900) return;
    int kk, nbase; float bias;
    if (col < 300)      { kk = 3; nbase = col * 3;                bias = b3[col]; }
    else if (col < 600) { kk = 5; nbase = 900 + (col - 300) * 5;  bias = b5[col - 300]; }
    else                { kk = 7; nbase = 2400 + (col - 600) * 7; bias = b7[col - 600]; }
    int p = kk >> 1;
    float best = 0.f;
    for (int h = 0; h < 8; h++) {
        float acc = bias;
        for (int r = 0; r < kk; r++) {
            int hp = h + r - p;
            if (hp >= 0 && hp < 8) acc += g_Csum[b * 8 + hp][nbase + r];
        }
        float v = acc > 0.f ? acc : 0.f;
        best = v > best ? v : best;
    }
    g_conv[b][col] = best;
}

// 5. Q/K/V matvecs: warp 0/1/2 -> Q/K/V for output t
__global__ void k_qkv(const float* __restrict__ wq, const float* __restrict__ bq,
                      const float* __restrict__ wk, const float* __restrict__ bk,
                      const float* __restrict__ wv, const float* __restrict__ bv) {
    int t = blockIdx.x, b = blockIdx.y;
    int w = threadIdx.x >> 5, lane = threadIdx.x & 31;
    const float* wm = (w == 0) ? wq : ((w == 1) ? wk : wv);
    const float* bm = (w == 0) ? bq : ((w == 1) ? bk : bv);
    const float* cv = g_conv[b];
    const float* row = wm + (size_t)t * 900;
    float acc = 0.f;
    for (int s = lane; s < 900; s += 32) acc += cv[s] * row[s];
#pragma unroll
    for (int o = 16; o; o >>= 1) acc += __shfl_down_sync(0xffffffffu, acc, o);
    if (lane == 0) {
        float val = acc + bm[t];
        if (w == 0) g_Q[b][t] = val;
        else if (w == 1) g_K[b][t] = val;
        else g_V[b][t] = val;
    }
}

// 6. attw[b][s][t] = softmax_t( K[b][s]*Q[b][t]/30 )
__global__ void k_attw() {
    __shared__ float qs[900];
    __shared__ float es[900];
    __shared__ float red[8];
    int s = blockIdx.x, b = blockIdx.y;
    int tid = threadIdx.x;
    for (int t = tid; t < 900; t += 256) qs[t] = g_Q[b][t];
    __syncthreads();
    float ks = g_K[b][s] * (1.0f / 30.0f);
    float mx = -1e30f;
    for (int t = tid; t < 900; t += 256) {
        float l = ks * qs[t];
        es[t] = l;
        mx = fmaxf(mx, l);
    }
#pragma unroll
    for (int o = 16; o; o >>= 1) mx = fmaxf(mx, __shfl_xor_sync(0xffffffffu, mx, o));
    if ((tid & 31) == 0) red[tid >> 5] = mx;
    __syncthreads();
    if (tid == 0) {
        float m2 = red[0];
        for (int i = 1; i < 8; i++) m2 = fmaxf(m2, red[i]);
        red[0] = m2;
    }
    __syncthreads();
    float bm = red[0];
    __syncthreads();
    float sum = 0.f;
    for (int t = tid; t < 900; t += 256) {
        float e = expf(es[t] - bm);
        es[t] = e;
        sum += e;
    }
#pragma unroll
    for (int o = 16; o; o >>= 1) sum += __shfl_xor_sync(0xffffffffu, sum, o);
    if ((tid & 31) == 0) red[tid >> 5] = sum;
    __syncthreads();
    if (tid == 0) {
        float z = 0.f;
        for (int i = 0; i < 8; i++) z += red[i];
        red[0] = z;
    }
    __syncthreads();
    float invz = 1.0f / red[0];
    for (int t = tid; t < 900; t += 256) g_attw[b][s][t] = es[t] * invz;
}

// 7. att[b][t] = sum_s V[b][s] * attw[b][s][t]
__global__ void k_attout() {
    __shared__ float vs[900];
    int b = blockIdx.y;
    int t = blockIdx.x * 256 + threadIdx.x;
    for (int s = threadIdx.x; s < 900; s += 256) vs[s] = g_V[b][s];
    __syncthreads();
    if (t >= 900) return;
    float acc = 0.f;
    for (int s = 0; s < 900; s++) acc += vs[s] * g_attw[b][s][t];
    g_att[b][t] = acc;
}

// 8. base = concat(conv, att) @ w1.T + b1 + b2 ; also seed s0 = base
__global__ void k_base(const float* __restrict__ w1, const float* __restrict__ b1,
                       const float* __restrict__ b2) {
    int wgl = blockIdx.x * 8 + (threadIdx.x >> 5);   // 0..7199
    int lane = threadIdx.x & 31;
    int b = wgl / 900, j = wgl - b * 900;
    const float* row = w1 + (size_t)j * 1800;
    const float* cv = g_conv[b];
    const float* av = g_att[b];
    float acc = 0.f;
    for (int s = lane; s < 900; s += 32)
        acc += cv[s] * row[s] + av[s] * row[900 + s];
#pragma unroll
    for (int o = 16; o; o >>= 1) acc += __shfl_down_sync(0xffffffffu, acc, o);
    if (lane == 0) {
        float v = acc + b1[j] + b2[j];
        g_base[b * 900 + j] = v;
        g_s0[b * 900 + j] = v;
    }
}

// 9. one scan step: out[b][j] = base[b][j] + sum_t in[b][t]*attw[b][i][t]*w2[j][t]
__global__ void k_step(const float* __restrict__ in, float* __restrict__ out,
                       int i, const float* __restrict__ w2) {
    int wgl = blockIdx.x * 8 + (threadIdx.x >> 5);
    int lane = threadIdx.x & 31;
    int b = wgl / 900, j = wgl - b * 900;
    const float* row = w2 + (size_t)j * 900;
    const float* sv = in + b * 900;
    const float* aw = g_attw[b][i];
    float acc = 0.f;
    for (int t = lane; t < 900; t += 32) acc += sv[t] * aw[t] * row[t];
#pragma unroll
    for (int o = 16; o; o >>= 1) acc += __shfl_down_sync(0xffffffffu, acc, o);
    if (lane == 0) out[b * 900 + j] = g_base[b * 900 + j] + acc;
}

extern "C" void kernel_launch(void* const* d_in, const int* in_sizes, int n_in,
                              void* d_out, int out_size) {
    const int*   x    = (const int*)d_in[0];
    const float* emb  = (const float*)d_in[1];
    const float* w3   = (const float*)d_in[2];
    const float* b3   = (const float*)d_in[3];
    const float* w5   = (const float*)d_in[4];
    const float* b5   = (const float*)d_in[5];
    const float* w7   = (const float*)d_in[6];
    const float* b7   = (const float*)d_in[7];
    const float* wq   = (const float*)d_in[8];
    const float* bq   = (const float*)d_in[9];
    const float* wk   = (const float*)d_in[10];
    const float* bk   = (const float*)d_in[11];
    const float* wv   = (const float*)d_in[12];
    const float* bv   = (const float*)d_in[13];
    const float* w1   = (const float*)d_in[14];
    const float* b1   = (const float*)d_in[15];
    const float* w2   = (const float*)d_in[16];
    const float* b2   = (const float*)d_in[17];
    float* out = (float*)d_out;

    k_build_E<<<dim3(KDIM / 256, M64), 256>>>(x, emb);
    k_gemm<<<dim3(NPAD / BN, SPLITK), 256>>>(w3, w5, w7);
    k_reduceC<<<(M64 * NPAD) / 256, 256>>>();
    k_pool<<<dim3(8, 8), 128>>>(b3, b5, b7);
    k_qkv<<<dim3(900, 8), 96>>>(wq, bq, wk, bk, wv, bv);
    k_attw<<<dim3(900, 8), 256>>>();
    k_attout<<<dim3(4, 8), 256>>>();
    k_base<<<900, 256>>>(w1, b1, b2);

    float* s0 = (float*)0;
    float* s1 = (float*)0;
    cudaGetSymbolAddress((void**)&s0, g_s0);
    cudaGetSymbolAddress((void**)&s1, g_s1);

    for (int step = 0; step < KT; step++) {
        int i = DD - KT + step;             // 892..899
        const float* src = (step & 1) ? s1 : s0;
        float* dst = (step == KT - 1) ? out : ((step & 1) ? s0 : s1);
        k_step<<<900, 256>>>(src, dst, i, w2);
    }
}

// round 17
// speedup vs baseline: 1.6116x; 1.6116x over previous
#include <cuda_runtime.h>
#include <cuda_bf16.h>
#include <math.h>

#define DD     900
#define M64    64
#define KDIM   32768
#define NPAD   4608
#define SPLITK 8
#define KCHUNK (KDIM/SPLITK)   // 4096
#define TN     128             // W rows per CTA tile
#define NSTAGE 64              // k per staged B buffer
#define NSTAGES (KCHUNK/NSTAGE) // 64
#define RS     144             // padded B smem row stride (bytes)
#define KT     8

// ------------------------- scratch (static, no allocs) ----------------------
__device__ __nv_bfloat16 g_Ehi[M64][KDIM];
__device__ __nv_bfloat16 g_Elo[M64][KDIM];
__device__ float g_CpartT[SPLITK][NPAD][M64];
__device__ float g_CsumT[NPAD][M64];
__device__ float g_conv[8][DD];
__device__ float g_Q[8][DD];
__device__ float g_K[8][DD];
__device__ float g_V[8][DD];
__device__ float g_attw[8][DD][DD];
__device__ float g_att[8][DD];
__device__ float g_base[8 * DD];
__device__ float g_s0[8 * DD];
__device__ float g_s1[8 * DD];

// ------------------------- helpers ------------------------------------------
__device__ __forceinline__ unsigned cvt_bf2(float lo, float hi) {
    unsigned r;  // lo -> low half, hi -> high half
    asm("cvt.rn.bf16x2.f32 %0, %1, %2;" : "=r"(r) : "f"(hi), "f"(lo));
    return r;
}
__device__ __forceinline__ void mma_bf16(float* d, const unsigned* a, const unsigned* b) {
    asm volatile("mma.sync.aligned.m16n8k16.row.col.f32.bf16.bf16.f32 "
                 "{%0,%1,%2,%3}, {%4,%5,%6,%7}, {%8,%9}, {%0,%1,%2,%3};"
                 : "+f"(d[0]), "+f"(d[1]), "+f"(d[2]), "+f"(d[3])
                 : "r"(a[0]), "r"(a[1]), "r"(a[2]), "r"(a[3]),
                   "r"(b[0]), "r"(b[1]));
}

// ---------------------------------------------------------------------------
// 1. gather + bf16 hi/lo split of E:  E[m][k=i*512+w] = emb[x[m,w]][i]
// ---------------------------------------------------------------------------
__global__ void k_build_E(const int* __restrict__ x, const float* __restrict__ emb) {
    int m = blockIdx.y;
    int k = blockIdx.x * 256 + threadIdx.x;
    int w = k & 511, i = k >> 9;
    float e = emb[x[m * 512 + w] * 64 + i];
    __nv_bfloat16 h = __float2bfloat16(e);
    g_Ehi[m][k] = h;
    g_Elo[m][k] = __float2bfloat16(e - __bfloat162float(h));
}

// ---------------------------------------------------------------------------
// 2. HMMA GEMM: CpartT[slab][n][m] = sum_{k in slab} W_n[k] * E[m][k]
//    A = W rows (16 per warp), f32 gmem -> in-register bf16 hi/lo fragments.
//    B = E hi/lo, double-buffered SMEM (conflict-free 144B rows).
//    3 precision passes per tile (hh, h*lo, lo*h), fp32 accum.
// ---------------------------------------------------------------------------
__global__ __launch_bounds__(256, 2) void k_gemm(const float* __restrict__ w3,
                                                 const float* __restrict__ w5,
                                                 const float* __restrict__ w7) {
    __shared__ const float* rowp[TN];
    __shared__ int ristr[TN];
    __shared__ __align__(16) unsigned char Bh[2][M64 * RS];
    __shared__ __align__(16) unsigned char Bl[2][M64 * RS];

    int tid = threadIdx.x;
    int w = tid >> 5, lane = tid & 31;
    int g = lane >> 2, tg = lane & 3;
    int n0 = blockIdx.x * TN, slab = blockIdx.y;

    if (tid < TN) {
        int n = n0 + tid;
        const float* arr = w3; int kk = 3, o = 0, r = 0;
        if (n < 900)       { o = n / 3;  r = n - o * 3; }
        else if (n < 2400) { arr = w5; kk = 5; int u = n - 900;  o = u / 5; r = u - o * 5; }
        else if (n < 4500) { arr = w7; kk = 7; int u = n - 2400; o = u / 7; r = u - o * 7; }
        rowp[tid]  = arr + (size_t)o * (64 * kk * 512) + r * 512;
        ristr[tid] = kk * 512;
    }
    __syncthreads();

    // A pointers for this lane's two fragment rows
    const float* p1 = rowp[w * 16 + g];      int st1 = ristr[w * 16 + g];
    const float* p2 = rowp[w * 16 + g + 8];  int st2 = ristr[w * 16 + g + 8];
    int kbase = slab * KCHUNK;

    // staging assignment: 256 threads cover 64n x {hi,lo} x 2 half-rows, 64B each
    int arr = tid >> 7, rr = tid & 127, sn = rr >> 1, sh = rr & 1;
    const __nv_bfloat16* sE = arr ? g_Elo[sn] : g_Ehi[sn];
    unsigned char* dst0 = (arr ? Bl[0] : Bh[0]) + sn * RS + sh * 64;
    unsigned char* dst1 = (arr ? Bl[1] : Bh[1]) + sn * RS + sh * 64;

    float acc[8][4];
#pragma unroll
    for (int j = 0; j < 8; j++)
#pragma unroll
        for (int q = 0; q < 4; q++) acc[j][q] = 0.f;

    // 2-deep A prefetch
    float2 Af[2][4];
#pragma unroll
    for (int p = 0; p < 2; p++) {
        int k0 = kbase + p * 16;
        int i0 = k0 >> 9, w0 = k0 & 511;
        const float* b1 = p1 + i0 * st1 + w0;
        const float* b2 = p2 + i0 * st2 + w0;
        Af[p][0] = *(const float2*)(b1 + 2 * tg);
        Af[p][1] = *(const float2*)(b2 + 2 * tg);
        Af[p][2] = *(const float2*)(b1 + 2 * tg + 8);
        Af[p][3] = *(const float2*)(b2 + 2 * tg + 8);
    }
    // stage 0 of B: each thread fills its full 64-byte region (4 x uint4)
    {
        const uint4* src = (const uint4*)(sE + kbase + sh * 32);
        uint4 v0 = src[0], v1 = src[1], v2 = src[2], v3 = src[3];
        *(uint4*)(dst0)      = v0;
        *(uint4*)(dst0 + 16) = v1;
        *(uint4*)(dst0 + 32) = v2;
        *(uint4*)(dst0 + 48) = v3;
    }
    __syncthreads();

    for (int s = 0; s < NSTAGES; s++) {
        int buf = s & 1;
        if (s + 1 < NSTAGES) {
            const uint4* src = (const uint4*)(sE + kbase + (s + 1) * NSTAGE + sh * 32);
            uint4 v0 = src[0], v1 = src[1], v2 = src[2], v3 = src[3];
            unsigned char* d = buf ? dst0 : dst1;
            *(uint4*)(d)      = v0;
            *(uint4*)(d + 16) = v1;
            *(uint4*)(d + 32) = v2;
            *(uint4*)(d + 48) = v3;
        }
        const unsigned char* bhB = Bh[buf];
        const unsigned char* blB = Bl[buf];

#pragma unroll
        for (int ks = 0; ks < 4; ks++) {
            int st = s * 4 + ks;
            int p = st & 1;
            // convert current A fragment to hi/lo
            unsigned ahi[4], alo[4];
#pragma unroll
            for (int q = 0; q < 4; q++) {
                float xx = Af[p][q].x, yy = Af[p][q].y;
                unsigned ux = __float_as_uint(xx), uy = __float_as_uint(yy);
                ahi[q] = __byte_perm(ux, uy, 0x7632);
                float lx = xx - __uint_as_float(ux & 0xFFFF0000u);
                float ly = yy - __uint_as_float(uy & 0xFFFF0000u);
                alo[q] = cvt_bf2(lx, ly);
            }
            // prefetch A for st+2
            if (st + 2 < 4 * NSTAGES) {
                int k0 = kbase + (st + 2) * 16;
                int i0 = k0 >> 9, w0 = k0 & 511;
                const float* b1 = p1 + i0 * st1 + w0;
                const float* b2 = p2 + i0 * st2 + w0;
                Af[p][0] = *(const float2*)(b1 + 2 * tg);
                Af[p][1] = *(const float2*)(b2 + 2 * tg);
                Af[p][2] = *(const float2*)(b1 + 2 * tg + 8);
                Af[p][3] = *(const float2*)(b2 + 2 * tg + 8);
            }
            int ko = ks * 32 + 4 * tg;     // byte offset of k-pair in row
#pragma unroll
            for (int j = 0; j < 8; j++) {
                int ro = (j * 8 + g) * RS + ko;
                unsigned bh[2], bl[2];
                bh[0] = *(const unsigned*)(bhB + ro);
                bh[1] = *(const unsigned*)(bhB + ro + 16);
                bl[0] = *(const unsigned*)(blB + ro);
                bl[1] = *(const unsigned*)(blB + ro + 16);
                mma_bf16(acc[j], ahi, bh);
                mma_bf16(acc[j], ahi, bl);
                mma_bf16(acc[j], alo, bh);
            }
        }
        __syncthreads();
    }

    // epilogue: D rows = W rows, cols = E rows
    int m1 = n0 + w * 16 + g;
    int m2 = m1 + 8;
#pragma unroll
    for (int j = 0; j < 8; j++) {
        int col = j * 8 + 2 * tg;
        float2 v0 = make_float2(acc[j][0], acc[j][1]);
        float2 v1 = make_float2(acc[j][2], acc[j][3]);
        *(float2*)&g_CpartT[slab][m1][col] = v0;
        *(float2*)&g_CpartT[slab][m2][col] = v1;
    }
}

// 3. split-K reduce
__global__ void k_reduceC() {
    int idx = blockIdx.x * 256 + threadIdx.x;
    const float* cp = (const float*)g_CpartT;
    float s = 0.f;
#pragma unroll
    for (int j = 0; j < SPLITK; j++) s += cp[(size_t)j * (NPAD * M64) + idx];
    ((float*)g_CsumT)[idx] = s;
}

// 4. bias + relu + max over H
__global__ void k_pool(const float* __restrict__ b3, const float* __restrict__ b5,
                       const float* __restrict__ b7) {
    int col = blockIdx.x * 128 + threadIdx.x;
    int b = blockIdx.y;
    if (col >= 900) return;
    int kk, nbase; float bias;
    if (col < 300)      { kk = 3; nbase = col * 3;                bias = b3[col]; }
    else if (col < 600) { kk = 5; nbase = 900 + (col - 300) * 5;  bias = b5[col - 300]; }
    else                { kk = 7; nbase = 2400 + (col - 600) * 7; bias = b7[col - 600]; }
    int p = kk >> 1;
    float vals[7][8];
#pragma unroll
    for (int r = 0; r < 7; r++) {
        if (r < kk) {
            float4 a0 = *(const float4*)&g_CsumT[nbase + r][b * 8];
            float4 a1 = *(const float4*)&g_CsumT[nbase + r][b * 8 + 4];
            vals[r][0] = a0.x; vals[r][1] = a0.y; vals[r][2] = a0.z; vals[r][3] = a0.w;
            vals[r][4] = a1.x; vals[r][5] = a1.y; vals[r][6] = a1.z; vals[r][7] = a1.w;
        }
    }
    float best = 0.f;
#pragma unroll
    for (int h = 0; h < 8; h++) {
        float acc = bias;
        for (int r = 0; r < kk; r++) {
            int hp = h + r - p;
            if (hp >= 0 && hp < 8) acc += vals[r][hp];
        }
        float v = acc > 0.f ? acc : 0.f;
        best = v > best ? v : best;
    }
    g_conv[b][col] = best;
}

// 5. Q/K/V matvecs
__global__ void k_qkv(const float* __restrict__ wq, const float* __restrict__ bq,
                      const float* __restrict__ wk, const float* __restrict__ bk,
                      const float* __restrict__ wv, const float* __restrict__ bv) {
    int t = blockIdx.x, b = blockIdx.y;
    int w = threadIdx.x >> 5, lane = threadIdx.x & 31;
    const float* wm = (w == 0) ? wq : ((w == 1) ? wk : wv);
    const float* bm = (w == 0) ? bq : ((w == 1) ? bk : bv);
    const float* cv = g_conv[b];
    const float* row = wm + (size_t)t * 900;
    float acc = 0.f;
    for (int s = lane; s < 900; s += 32) acc += cv[s] * row[s];
#pragma unroll
    for (int o = 16; o; o >>= 1) acc += __shfl_down_sync(0xffffffffu, acc, o);
    if (lane == 0) {
        float val = acc + bm[t];
        if (w == 0) g_Q[b][t] = val;
        else if (w == 1) g_K[b][t] = val;
        else g_V[b][t] = val;
    }
}

// 6. attw rows (softmax over t)
__global__ void k_attw() {
    __shared__ float qs[900];
    __shared__ float es[900];
    __shared__ float red[8];
    int s = blockIdx.x, b = blockIdx.y;
    int tid = threadIdx.x;
    for (int t = tid; t < 900; t += 256) qs[t] = g_Q[b][t];
    __syncthreads();
    float ks = g_K[b][s] * (1.0f / 30.0f);
    float mx = -1e30f;
    for (int t = tid; t < 900; t += 256) {
        float l = ks * qs[t];
        es[t] = l;
        mx = fmaxf(mx, l);
    }
#pragma unroll
    for (int o = 16; o; o >>= 1) mx = fmaxf(mx, __shfl_xor_sync(0xffffffffu, mx, o));
    if ((tid & 31) == 0) red[tid >> 5] = mx;
    __syncthreads();
    if (tid == 0) {
        float m2 = red[0];
        for (int i = 1; i < 8; i++) m2 = fmaxf(m2, red[i]);
        red[0] = m2;
    }
    __syncthreads();
    float bm = red[0];
    __syncthreads();
    float sum = 0.f;
    for (int t = tid; t < 900; t += 256) {
        float e = expf(es[t] - bm);
        es[t] = e;
        sum += e;
    }
#pragma unroll
    for (int o = 16; o; o >>= 1) sum += __shfl_xor_sync(0xffffffffu, sum, o);
    if ((tid & 31) == 0) red[tid >> 5] = sum;
    __syncthreads();
    if (tid == 0) {
        float z = 0.f;
        for (int i = 0; i < 8; i++) z += red[i];
        red[0] = z;
    }
    __syncthreads();
    float invz = 1.0f / red[0];
    for (int t = tid; t < 900; t += 256) g_attw[b][s][t] = es[t] * invz;
}

// 7. att[b][t] = sum_s V[b][s] * attw[b][s][t]
__global__ void k_attout() {
    __shared__ float vs[900];
    int b = blockIdx.y;
    int t = blockIdx.x * 256 + threadIdx.x;
    for (int s = threadIdx.x; s < 900; s += 256) vs[s] = g_V[b][s];
    __syncthreads();
    if (t >= 900) return;
    float acc = 0.f;
    for (int s = 0; s < 900; s++) acc += vs[s] * g_attw[b][s][t];
    g_att[b][t] = acc;
}

// 8. base = concat(conv, att) @ w1.T + b1 + b2 ; seed s0
__global__ void k_base(const float* __restrict__ w1, const float* __restrict__ b1,
                       const float* __restrict__ b2) {
    int wgl = blockIdx.x * 8 + (threadIdx.x >> 5);
    int lane = threadIdx.x & 31;
    int b = wgl / 900, j = wgl - b * 900;
    const float* row = w1 + (size_t)j * 1800;
    const float* cv = g_conv[b];
    const float* av = g_att[b];
    float acc = 0.f;
    for (int s = lane; s < 900; s += 32)
        acc += cv[s] * row[s] + av[s] * row[900 + s];
#pragma unroll
    for (int o = 16; o; o >>= 1) acc += __shfl_down_sync(0xffffffffu, acc, o);
    if (lane == 0) {
        float v = acc + b1[j] + b2[j];
        g_base[b * 900 + j] = v;
        g_s0[b * 900 + j] = v;
    }
}

// 9. one scan step
__global__ void k_step(const float* __restrict__ in, float* __restrict__ out,
                       int i, const float* __restrict__ w2) {
    int wgl = blockIdx.x * 8 + (threadIdx.x >> 5);
    int lane = threadIdx.x & 31;
    int b = wgl / 900, j = wgl - b * 900;
    const float* row = w2 + (size_t)j * 900;
    const float* sv = in + b * 900;
    const float* aw = g_attw[b][i];
    float acc = 0.f;
    for (int t = lane; t < 900; t += 32) acc += sv[t] * aw[t] * row[t];
#pragma unroll
    for (int o = 16; o; o >>= 1) acc += __shfl_down_sync(0xffffffffu, acc, o);
    if (lane == 0) out[b * 900 + j] = g_base[b * 900 + j] + acc;
}

extern "C" void kernel_launch(void* const* d_in, const int* in_sizes, int n_in,
                              void* d_out, int out_size) {
    const int*   x    = (const int*)d_in[0];
    const float* emb  = (const float*)d_in[1];
    const float* w3   = (const float*)d_in[2];
    const float* b3   = (const float*)d_in[3];
    const float* w5   = (const float*)d_in[4];
    const float* b5   = (const float*)d_in[5];
    const float* w7   = (const float*)d_in[6];
    const float* b7   = (const float*)d_in[7];
    const float* wq   = (const float*)d_in[8];
    const float* bq   = (const float*)d_in[9];
    const float* wk   = (const float*)d_in[10];
    const float* bk   = (const float*)d_in[11];
    const float* wv   = (const float*)d_in[12];
    const float* bv   = (const float*)d_in[13];
    const float* w1   = (const float*)d_in[14];
    const float* b1   = (const float*)d_in[15];
    const float* w2   = (const float*)d_in[16];
    const float* b2   = (const float*)d_in[17];
    float* out = (float*)d_out;

    k_build_E<<<dim3(KDIM / 256, M64), 256>>>(x, emb);
    k_gemm<<<dim3(NPAD / TN, SPLITK), 256>>>(w3, w5, w7);
    k_reduceC<<<(NPAD * M64) / 256, 256>>>();
    k_pool<<<dim3(8, 8), 128>>>(b3, b5, b7);
    k_qkv<<<dim3(900, 8), 96>>>(wq, bq, wk, bk, wv, bv);
    k_attw<<<dim3(900, 8), 256>>>();
    k_attout<<<dim3(4, 8), 256>>>();
    k_base<<<900, 256>>>(w1, b1, b2);

    float* s0 = (float*)0;
    float* s1 = (float*)0;
    cudaGetSymbolAddress((void**)&s0, g_s0);
    cudaGetSymbolAddress((void**)&s1, g_s1);

    for (int step = 0; step < KT; step++) {
        int i = DD - KT + step;             // 892..899
        const float* src = (step & 1) ? s1 : s0;
        float* dst = (step == KT - 1) ? out : ((step & 1) ? s0 : s1);
        k_step<<<900, 256>>>(src, dst, i, w2);
    }
}